// round 1
// baseline (speedup 1.0000x reference)
#include <cuda_runtime.h>
#include <math.h>

#define BLOCK 256
#define MAX_BLOCKS 8192

__device__ float g_partials[MAX_BLOCKS];

__device__ __forceinline__ void box_corners(float x, float y, float w, float h, float a,
                                            float* cx, float* cy) {
    float s, c;
    sincosf(a, &s, &c);
    float hw = 0.5f * w, hh = 0.5f * h;
    // CCW order: (-hw,-hh), (hw,-hh), (hw,hh), (-hw,hh)
    const float dx[4] = {-hw, hw, hw, -hw};
    const float dy[4] = {-hh, -hh, hh, hh};
#pragma unroll
    for (int k = 0; k < 4; k++) {
        cx[k] = x + dx[k] * c - dy[k] * s;
        cy[k] = y + dx[k] * s + dy[k] * c;
    }
}

__global__ void __launch_bounds__(BLOCK)
rot_iou_loss_kernel(const float* __restrict__ pred,
                    const float* __restrict__ tgt,
                    int n) {
    int i = blockIdx.x * blockDim.x + threadIdx.x;
    float loss = 0.0f;
    if (i < n) {
        const float* p = pred + 5ll * i;
        const float* t = tgt + 5ll * i;
        float x1 = p[0], y1 = p[1], w1 = p[2], h1 = p[3], a1 = p[4];
        float x2 = t[0], y2 = t[1], w2 = t[2], h2 = t[3], a2 = t[4];

        float area1 = w1 * h1;
        float area2 = w2 * h2;

        // corners
        float ax[4], ay[4];   // subject (pred)
        float bx[4], by[4];   // clip (target)
        box_corners(x1, y1, w1, h1, a1, ax, ay);
        box_corners(x2, y2, w2, h2, a2, bx, by);

        // Sutherland-Hodgman: clip subject quad by the 4 CCW edges of clip quad.
        float px[2][8], py[2][8];
        int cur = 0;
        int np = 4;
#pragma unroll
        for (int k = 0; k < 4; k++) { px[0][k] = ax[k]; py[0][k] = ay[k]; }

#pragma unroll
        for (int e = 0; e < 4; e++) {
            if (np == 0) break;
            float ex0 = bx[e],          ey0 = by[e];
            float ex1 = bx[(e + 1) & 3], ey1 = by[(e + 1) & 3];
            float edx = ex1 - ex0, edy = ey1 - ey0;
            int nxt = cur ^ 1;
            int m = 0;
            for (int k = 0; k < np; k++) {
                int kn = (k + 1 == np) ? 0 : k + 1;
                float pxk = px[cur][k],  pyk = py[cur][k];
                float pxn = px[cur][kn], pyn = py[cur][kn];
                float dk = edx * (pyk - ey0) - edy * (pxk - ex0);
                float dn = edx * (pyn - ey0) - edy * (pxn - ex0);
                bool ink = (dk >= 0.0f);
                bool inn = (dn >= 0.0f);
                if (ink) { px[nxt][m] = pxk; py[nxt][m] = pyk; m++; }
                if (ink != inn) {
                    float tpar = dk / (dk - dn);
                    px[nxt][m] = pxk + tpar * (pxn - pxk);
                    py[nxt][m] = pyk + tpar * (pyn - pyk);
                    m++;
                }
            }
            cur = nxt;
            np = m;
        }

        // shoelace
        float twice_area = 0.0f;
        for (int k = 0; k < np; k++) {
            int kn = (k + 1 == np) ? 0 : k + 1;
            twice_area += px[cur][k] * py[cur][kn] - px[cur][kn] * py[cur][k];
        }
        float inter = 0.5f * fabsf(twice_area);
        if (np < 3) inter = 0.0f;

        float iou = inter / (area1 + area2 - inter);
        iou = fmaxf(iou, 1e-6f);
        loss = 1.0f - iou * iou * iou;
    }

    // block reduction
    __shared__ float sdata[BLOCK];
    int tid = threadIdx.x;
    sdata[tid] = loss;
    __syncthreads();
#pragma unroll
    for (int s = BLOCK / 2; s >= 32; s >>= 1) {
        if (tid < s) sdata[tid] += sdata[tid + s];
        __syncthreads();
    }
    if (tid < 32) {
        float v = sdata[tid];
#pragma unroll
        for (int off = 16; off > 0; off >>= 1)
            v += __shfl_down_sync(0xFFFFFFFFu, v, off);
        if (tid == 0) g_partials[blockIdx.x] = v;
    }
}

__global__ void __launch_bounds__(BLOCK)
final_reduce_kernel(float* __restrict__ out, int nblocks, float inv_n) {
    __shared__ double sdata[BLOCK];
    int tid = threadIdx.x;
    double s = 0.0;
    for (int j = tid; j < nblocks; j += BLOCK) s += (double)g_partials[j];
    sdata[tid] = s;
    __syncthreads();
#pragma unroll
    for (int st = BLOCK / 2; st > 0; st >>= 1) {
        if (tid < st) sdata[tid] += sdata[tid + st];
        __syncthreads();
    }
    if (tid == 0) out[0] = (float)(sdata[0] * (double)inv_n);
}

extern "C" void kernel_launch(void* const* d_in, const int* in_sizes, int n_in,
                              void* d_out, int out_size) {
    const float* pred = (const float*)d_in[0];
    const float* tgt  = (const float*)d_in[1];
    int n = in_sizes[0] / 5;
    int nblocks = (n + BLOCK - 1) / BLOCK;
    rot_iou_loss_kernel<<<nblocks, BLOCK>>>(pred, tgt, n);
    final_reduce_kernel<<<1, BLOCK>>>((float*)d_out, nblocks, 1.0f / (float)n);
}

// round 2
// speedup vs baseline: 1.0817x; 1.0817x over previous
#include <cuda_runtime.h>
#include <math.h>

#define BLOCK 256
#define MAX_BLOCKS 8192

__device__ float g_partials[MAX_BLOCKS];
__device__ unsigned int g_count = 0;

// Clip a convex polygon (in local memory / registers) against one slab edge.
// MODE: 0: x <= hw   1: x >= -hw   2: y <= hh   3: y >= -hh
template <int MODE, int MAXIN>
__device__ __forceinline__ int clip_pass(const float2* in, int np, float2* out,
                                         float hw, float hh) {
    if (np == 0) return 0;
    int m = 0;
    float2 first = in[0];
    float2 prev = first;
    float dprev;
    if (MODE == 0) dprev = hw - first.x;
    else if (MODE == 1) dprev = first.x + hw;
    else if (MODE == 2) dprev = hh - first.y;
    else dprev = first.y + hh;
#pragma unroll
    for (int k = 1; k <= MAXIN; k++) {
        if (k > np) break;
        float2 cur = (k == np) ? first : in[k];
        float dcur;
        if (MODE == 0) dcur = hw - cur.x;
        else if (MODE == 1) dcur = cur.x + hw;
        else if (MODE == 2) dcur = hh - cur.y;
        else dcur = cur.y + hh;
        bool inp = (dprev >= 0.0f);
        bool inc = (dcur >= 0.0f);
        if (inp) out[m++] = prev;
        if (inp != inc) {
            float t = __fdividef(dprev, dprev - dcur);
            out[m++] = make_float2(fmaf(t, cur.x - prev.x, prev.x),
                                   fmaf(t, cur.y - prev.y, prev.y));
        }
        prev = cur;
        dprev = dcur;
    }
    return m;
}

__global__ void __launch_bounds__(BLOCK)
rot_iou_loss_kernel(const float* __restrict__ pred,
                    const float* __restrict__ tgt,
                    float* __restrict__ out,
                    int n, int nblocks, float inv_n) {
    int i = blockIdx.x * blockDim.x + threadIdx.x;
    float loss = 0.0f;
    if (i < n) {
        const float* p = pred + 5ll * i;
        const float* t = tgt + 5ll * i;
        float x1 = p[0], y1 = p[1], w1 = p[2], h1 = p[3], a1 = p[4];
        float x2 = t[0], y2 = t[1], w2 = t[2], h2 = t[3], a2 = t[4];

        float area1 = w1 * h1;
        float area2 = w2 * h2;

        // Transform into box1's local frame: box1 -> axis-aligned slab.
        float s1, c1;
        sincosf(a1, &s1, &c1);
        float rdx = x2 - x1, rdy = y2 - y1;
        float cx = rdx * c1 + rdy * s1;
        float cy = -rdx * s1 + rdy * c1;
        float sr, cr;
        sincosf(a2 - a1, &sr, &cr);
        float hw2 = 0.5f * w2, hh2 = 0.5f * h2;
        float e1x = hw2 * cr, e1y = hw2 * sr;   // half-edge along box2 width
        float e2x = -hh2 * sr, e2y = hh2 * cr;  // half-edge along box2 height

        float2 q[4];  // box2 corners in box1 frame (CCW), register-resident
        q[0] = make_float2(cx - e1x - e2x, cy - e1y - e2y);
        q[1] = make_float2(cx + e1x - e2x, cy + e1y - e2y);
        q[2] = make_float2(cx + e1x + e2x, cy + e1y + e2y);
        q[3] = make_float2(cx - e1x + e2x, cy - e1y + e2y);

        float hw = 0.5f * w1, hh = 0.5f * h1;

        float2 buf0[8], buf1[8];
        int np;
        np = clip_pass<0, 4>(q, 4, buf0, hw, hh);     // max 5
        np = clip_pass<1, 5>(buf0, np, buf1, hw, hh); // max 6
        np = clip_pass<2, 6>(buf1, np, buf0, hw, hh); // max 7
        np = clip_pass<3, 7>(buf0, np, buf1, hw, hh); // max 8

        // shoelace (single walk, wrap via carried first vertex)
        float inter = 0.0f;
        if (np >= 3) {
            float2 first = buf1[0];
            float2 prev = first;
            float acc = 0.0f;
#pragma unroll
            for (int k = 1; k <= 8; k++) {
                if (k > np) break;
                float2 cur = (k == np) ? first : buf1[k];
                acc += prev.x * cur.y - prev.y * cur.x;
                prev = cur;
            }
            inter = 0.5f * fabsf(acc);
        }

        float iou = inter / (area1 + area2 - inter);
        iou = fmaxf(iou, 1e-6f);
        loss = 1.0f - iou * iou * iou;
    }

    // in-block reduction (fixed order -> deterministic)
    __shared__ float sdata[BLOCK / 32];
    int tid = threadIdx.x;
    float v = loss;
#pragma unroll
    for (int off = 16; off > 0; off >>= 1)
        v += __shfl_down_sync(0xFFFFFFFFu, v, off);
    if ((tid & 31) == 0) sdata[tid >> 5] = v;
    __syncthreads();
    if (tid < 32) {
        float w = (tid < BLOCK / 32) ? sdata[tid] : 0.0f;
#pragma unroll
        for (int off = 4; off > 0; off >>= 1)
            w += __shfl_down_sync(0xFFFFFFFFu, w, off);
        if (tid == 0) g_partials[blockIdx.x] = w;
    }

    // last-block final reduction (deterministic index-order sum)
    __shared__ bool is_last;
    __threadfence();
    if (tid == 0) {
        unsigned int c = atomicAdd(&g_count, 1u);
        is_last = (c == (unsigned int)nblocks - 1u);
    }
    __syncthreads();
    if (is_last) {
        __shared__ double dd[BLOCK];
        double s = 0.0;
        for (int j = tid; j < nblocks; j += BLOCK) s += (double)g_partials[j];
        dd[tid] = s;
        __syncthreads();
#pragma unroll
        for (int st = BLOCK / 2; st > 0; st >>= 1) {
            if (tid < st) dd[tid] += dd[tid + st];
            __syncthreads();
        }
        if (tid == 0) {
            out[0] = (float)(dd[0] * (double)inv_n);
            g_count = 0;  // reset for next graph replay
        }
    }
}

extern "C" void kernel_launch(void* const* d_in, const int* in_sizes, int n_in,
                              void* d_out, int out_size) {
    const float* pred = (const float*)d_in[0];
    const float* tgt  = (const float*)d_in[1];
    int n = in_sizes[0] / 5;
    int nblocks = (n + BLOCK - 1) / BLOCK;
    rot_iou_loss_kernel<<<nblocks, BLOCK>>>(pred, tgt, (float*)d_out,
                                            n, nblocks, 1.0f / (float)n);
}

// round 3
// speedup vs baseline: 2.1467x; 1.9846x over previous
#include <cuda_runtime.h>
#include <math.h>

#define BLOCK 256
#define MAX_BLOCKS 8192

__device__ float g_partials[MAX_BLOCKS];
__device__ unsigned int g_count = 0;

__global__ void __launch_bounds__(BLOCK)
rot_iou_loss_kernel(const float* __restrict__ pred,
                    const float* __restrict__ tgt,
                    float* __restrict__ out,
                    int n, int nblocks, float inv_n) {
    int i = blockIdx.x * blockDim.x + threadIdx.x;
    float loss = 0.0f;
    if (i < n) {
        const float* p = pred + 5ll * i;
        const float* t = tgt + 5ll * i;
        float x1 = p[0], y1 = p[1], w1 = p[2], h1 = p[3], a1 = p[4];
        float x2 = t[0], y2 = t[1], w2 = t[2], h2 = t[3], a2 = t[4];

        float area1 = w1 * h1;
        float area2 = w2 * h2;

        // Box1's local frame: box1 becomes the axis-aligned box [±hw]x[±hh].
        float s1, c1;
        sincosf(a1, &s1, &c1);
        float rdx = x2 - x1, rdy = y2 - y1;
        float cx = rdx * c1 + rdy * s1;
        float cy = -rdx * s1 + rdy * c1;
        float sr, cr;
        sincosf(a2 - a1, &sr, &cr);
        float hw2 = 0.5f * w2, hh2 = 0.5f * h2;
        float e1x = hw2 * cr, e1y = hw2 * sr;
        float e2x = -hh2 * sr, e2y = hh2 * cr;

        // box2 corners in box1 frame (CCW), register-resident
        float2 q[4];
        q[0] = make_float2(cx - e1x - e2x, cy - e1y - e2y);
        q[1] = make_float2(cx + e1x - e2x, cy + e1y - e2y);
        q[2] = make_float2(cx + e1x + e2x, cy + e1y + e2y);
        q[3] = make_float2(cx - e1x + e2x, cy - e1y + e2y);

        float hw = 0.5f * w1, hh = 0.5f * h1;

        // ---- Pass 1: clip quad against x-slab |x| <= hw (both planes fused).
        // Convex polygon vs slab: output <= 6 vertices, correct in one pass.
        float2 buf[6];
        int np = 0;
#pragma unroll
        for (int k = 0; k < 4; k++) {
            float2 P = q[k];
            float2 C = q[(k + 1) & 3];
            float d0p = hw - P.x, d0c = hw - C.x;   // plane x <= hw
            float d1p = P.x + hw, d1c = C.x + hw;   // plane x >= -hw
            bool insideP = (d0p >= 0.0f) & (d1p >= 0.0f);
            if (insideP) buf[np++] = P;
            bool c0 = (d0p >= 0.0f) != (d0c >= 0.0f);
            bool c1 = (d1p >= 0.0f) != (d1c >= 0.0f);
            float t0 = __fdividef(d0p, d0p - d0c);
            float t1 = __fdividef(d1p, d1p - d1c);
            float2 i0 = make_float2(fmaf(t0, C.x - P.x, P.x), fmaf(t0, C.y - P.y, P.y));
            float2 i1 = make_float2(fmaf(t1, C.x - P.x, P.x), fmaf(t1, C.y - P.y, P.y));
            if (c0 & c1) {
                if (t0 < t1) { buf[np++] = i0; buf[np++] = i1; }
                else         { buf[np++] = i1; buf[np++] = i0; }
            } else if (c0) {
                buf[np++] = i0;
            } else if (c1) {
                buf[np++] = i1;
            }
        }

        // ---- Pass 2: clip against y-slab |y| <= hh, streaming shoelace.
        float acc = 0.0f;
        int m = 0;
        float2 first, prev;
        if (np >= 3) {
            float2 Pfirst = buf[0];
            float2 P = Pfirst;
#pragma unroll
            for (int k = 1; k <= 6; k++) {
                if (k > np) break;
                float2 C = (k == np) ? Pfirst : buf[k];
                float d0p = hh - P.y, d0c = hh - C.y;   // y <= hh
                float d1p = P.y + hh, d1c = C.y + hh;   // y >= -hh
                bool insideP = (d0p >= 0.0f) & (d1p >= 0.0f);
                bool c0 = (d0p >= 0.0f) != (d0c >= 0.0f);
                bool c1 = (d1p >= 0.0f) != (d1c >= 0.0f);
                float t0 = __fdividef(d0p, d0p - d0c);
                float t1 = __fdividef(d1p, d1p - d1c);
                float2 i0 = make_float2(fmaf(t0, C.x - P.x, P.x), fmaf(t0, C.y - P.y, P.y));
                float2 i1 = make_float2(fmaf(t1, C.x - P.x, P.x), fmaf(t1, C.y - P.y, P.y));

                // streaming emit: first/prev carried, shoelace accumulated
                if (insideP) {
                    if (m == 0) first = P;
                    else acc += prev.x * P.y - prev.y * P.x;
                    prev = P; m++;
                }
                float2 e0 = (c0 & c1 & (t1 < t0)) ? i1 : i0;
                float2 e1 = (c0 & c1 & (t1 < t0)) ? i0 : i1;
                if (c0 & c1) {
                    if (m == 0) first = e0;
                    else acc += prev.x * e0.y - prev.y * e0.x;
                    prev = e0; m++;
                    acc += prev.x * e1.y - prev.y * e1.x;
                    prev = e1; m++;
                } else if (c0 | c1) {
                    float2 e = c0 ? i0 : i1;
                    if (m == 0) first = e;
                    else acc += prev.x * e.y - prev.y * e.x;
                    prev = e; m++;
                }
                P = C;
            }
        }

        float inter = 0.0f;
        if (m >= 3) {
            acc += prev.x * first.y - prev.y * first.x;
            inter = 0.5f * fabsf(acc);
        }

        float iou = inter / (area1 + area2 - inter);
        iou = fmaxf(iou, 1e-6f);
        loss = 1.0f - iou * iou * iou;
    }

    // in-block reduction (fixed order -> deterministic)
    __shared__ float sdata[BLOCK / 32];
    int tid = threadIdx.x;
    float v = loss;
#pragma unroll
    for (int off = 16; off > 0; off >>= 1)
        v += __shfl_down_sync(0xFFFFFFFFu, v, off);
    if ((tid & 31) == 0) sdata[tid >> 5] = v;
    __syncthreads();
    if (tid < 32) {
        float w = (tid < BLOCK / 32) ? sdata[tid] : 0.0f;
#pragma unroll
        for (int off = 4; off > 0; off >>= 1)
            w += __shfl_down_sync(0xFFFFFFFFu, w, off);
        if (tid == 0) g_partials[blockIdx.x] = w;
    }

    // last-block final reduction (deterministic index-order sum)
    __shared__ bool is_last;
    __threadfence();
    if (tid == 0) {
        unsigned int c = atomicAdd(&g_count, 1u);
        is_last = (c == (unsigned int)nblocks - 1u);
    }
    __syncthreads();
    if (is_last) {
        __shared__ double dd[BLOCK];
        double s = 0.0;
        for (int j = tid; j < nblocks; j += BLOCK) s += (double)g_partials[j];
        dd[tid] = s;
        __syncthreads();
#pragma unroll
        for (int st = BLOCK / 2; st > 0; st >>= 1) {
            if (tid < st) dd[tid] += dd[tid + st];
            __syncthreads();
        }
        if (tid == 0) {
            out[0] = (float)(dd[0] * (double)inv_n);
            g_count = 0;  // reset for next graph replay
        }
    }
}

extern "C" void kernel_launch(void* const* d_in, const int* in_sizes, int n_in,
                              void* d_out, int out_size) {
    const float* pred = (const float*)d_in[0];
    const float* tgt  = (const float*)d_in[1];
    int n = in_sizes[0] / 5;
    int nblocks = (n + BLOCK - 1) / BLOCK;
    rot_iou_loss_kernel<<<nblocks, BLOCK>>>(pred, tgt, (float*)d_out,
                                            n, nblocks, 1.0f / (float)n);
}

// round 4
// speedup vs baseline: 2.8417x; 1.3237x over previous
#include <cuda_runtime.h>
#include <math.h>

#define BLOCK 256
#define MAX_BLOCKS 8192

__device__ float g_partials[MAX_BLOCKS];
__device__ unsigned int g_count = 0;

#define CE(a, b) { float _lo = fminf(a, b); float _hi = fmaxf(a, b); a = _lo; b = _hi; }

__global__ void __launch_bounds__(BLOCK)
rot_iou_loss_kernel(const float* __restrict__ pred,
                    const float* __restrict__ tgt,
                    float* __restrict__ out,
                    int n, int nblocks, float inv_n) {
    int i = blockIdx.x * blockDim.x + threadIdx.x;
    float loss = 0.0f;
    if (i < n) {
        const float* p = pred + 5ll * i;
        const float* t = tgt + 5ll * i;
        float x1 = p[0], y1 = p[1], w1 = p[2], h1 = p[3], a1 = p[4];
        float x2 = t[0], y2 = t[1], w2 = t[2], h2 = t[3], a2 = t[4];

        float area1 = w1 * h1;
        float area2 = w2 * h2;

        // Box1's local frame: box1 -> axis-aligned box [-hw,hw]x[-hh,hh].
        float s1, c1;
        sincosf(a1, &s1, &c1);
        float rdx0 = x2 - x1, rdy0 = y2 - y1;
        float cx = rdx0 * c1 + rdy0 * s1;
        float cy = -rdx0 * s1 + rdy0 * c1;
        float sr, cr;
        sincosf(a2 - a1, &sr, &cr);
        float hw2 = 0.5f * w2, hh2 = 0.5f * h2;
        float e1x = hw2 * cr, e1y = hw2 * sr;
        float e2x = -hh2 * sr, e2y = hh2 * cr;

        // box2 corners in box1 frame (CCW), register-resident
        float qx[4], qy[4];
        qx[0] = cx - e1x - e2x; qy[0] = cy - e1y - e2y;
        qx[1] = cx + e1x - e2x; qy[1] = cy + e1y - e2y;
        qx[2] = cx + e1x + e2x; qy[2] = cy + e1y + e2y;
        qx[3] = cx - e1x + e2x; qy[3] = cy - e1y + e2y;

        float hw = 0.5f * w1, hh = 0.5f * h1;

        // Clamp-integration: signed area of clamp(boundary of box2) onto box1
        // equals area(box1 ∩ box2). Fully branchless.
        float acc = 0.0f;
        // carried clamped endpoint
        float pcx = fminf(fmaxf(qx[0], -hw), hw);
        float pcy = fminf(fmaxf(qy[0], -hh), hh);
        float firstx = pcx, firsty = pcy;

#pragma unroll
        for (int k = 0; k < 4; k++) {
            float Px = qx[k], Py = qy[k];
            int kn = (k + 1) & 3;
            float Cx = qx[kn], Cy = qy[kn];
            float Dx = Cx - Px, Dy = Cy - Py;
            float rdx = __fdividef(1.0f, Dx);
            float rdy = __fdividef(1.0f, Dy);

            // crossing parameters with the 4 clamp lines, clamped to [0,1]
            float t0 = (hw - Px) * rdx;
            float t1 = (-hw - Px) * rdx;
            float t2 = (hh - Py) * rdy;
            float t3 = (-hh - Py) * rdy;
            // NaN/inf -> clamp to 0 (duplicate point, zero contribution)
            t0 = fminf(fmaxf(t0, 0.0f), 1.0f);
            t1 = fminf(fmaxf(t1, 0.0f), 1.0f);
            t2 = fminf(fmaxf(t2, 0.0f), 1.0f);
            t3 = fminf(fmaxf(t3, 0.0f), 1.0f);

            // sort 4 (network: 5 compare-exchanges)
            CE(t0, t1); CE(t2, t3); CE(t0, t2); CE(t1, t3); CE(t1, t2);

            // breakpoints, clamped into the box; shoelace against carried point
            float bx, by;
#pragma unroll
            for (int j = 0; j < 4; j++) {
                float tj = (j == 0) ? t0 : (j == 1) ? t1 : (j == 2) ? t2 : t3;
                bx = fminf(fmaxf(fmaf(tj, Dx, Px), -hw), hw);
                by = fminf(fmaxf(fmaf(tj, Dy, Py), -hh), hh);
                acc += pcx * by - pcy * bx;
                pcx = bx; pcy = by;
            }
            // clamped far endpoint (becomes next edge's carried point)
            bx = fminf(fmaxf(Cx, -hw), hw);
            by = fminf(fmaxf(Cy, -hh), hh);
            acc += pcx * by - pcy * bx;
            pcx = bx; pcy = by;
        }
        // close the loop (pc == first by construction, but keep exact closure)
        acc += pcx * firsty - pcy * firstx;

        float inter = 0.5f * fabsf(acc);
        float iou = inter / (area1 + area2 - inter);
        iou = fmaxf(iou, 1e-6f);
        loss = 1.0f - iou * iou * iou;
    }

    // in-block reduction (fixed order -> deterministic)
    __shared__ float sdata[BLOCK / 32];
    int tid = threadIdx.x;
    float v = loss;
#pragma unroll
    for (int off = 16; off > 0; off >>= 1)
        v += __shfl_down_sync(0xFFFFFFFFu, v, off);
    if ((tid & 31) == 0) sdata[tid >> 5] = v;
    __syncthreads();
    if (tid < 32) {
        float w = (tid < BLOCK / 32) ? sdata[tid] : 0.0f;
#pragma unroll
        for (int off = 4; off > 0; off >>= 1)
            w += __shfl_down_sync(0xFFFFFFFFu, w, off);
        if (tid == 0) g_partials[blockIdx.x] = w;
    }

    // last-block final reduction (deterministic index-order sum)
    __shared__ bool is_last;
    __threadfence();
    if (tid == 0) {
        unsigned int c = atomicAdd(&g_count, 1u);
        is_last = (c == (unsigned int)nblocks - 1u);
    }
    __syncthreads();
    if (is_last) {
        __shared__ double dd[BLOCK];
        double s = 0.0;
        for (int j = tid; j < nblocks; j += BLOCK) s += (double)g_partials[j];
        dd[tid] = s;
        __syncthreads();
#pragma unroll
        for (int st = BLOCK / 2; st > 0; st >>= 1) {
            if (tid < st) dd[tid] += dd[tid + st];
            __syncthreads();
        }
        if (tid == 0) {
            out[0] = (float)(dd[0] * (double)inv_n);
            g_count = 0;  // reset for next graph replay
        }
    }
}

extern "C" void kernel_launch(void* const* d_in, const int* in_sizes, int n_in,
                              void* d_out, int out_size) {
    const float* pred = (const float*)d_in[0];
    const float* tgt  = (const float*)d_in[1];
    int n = in_sizes[0] / 5;
    int nblocks = (n + BLOCK - 1) / BLOCK;
    rot_iou_loss_kernel<<<nblocks, BLOCK>>>(pred, tgt, (float*)d_out,
                                            n, nblocks, 1.0f / (float)n);
}

// round 5
// speedup vs baseline: 3.2555x; 1.1456x over previous
#include <cuda_runtime.h>
#include <math.h>

#define BLOCK 256
#define MAX_BLOCKS 8192

__device__ float g_partials[MAX_BLOCKS];
__device__ unsigned int g_count = 0;

#define CE(a, b) { float _lo = fminf(a, b); float _hi = fmaxf(a, b); a = _lo; b = _hi; }

__device__ __forceinline__ float pair_loss(const float* __restrict__ pred,
                                           const float* __restrict__ tgt,
                                           int i) {
    const float* p = pred + 5ll * i;
    const float* t = tgt + 5ll * i;
    float x1 = p[0], y1 = p[1], w1 = p[2], h1 = p[3], a1 = p[4];
    float x2 = t[0], y2 = t[1], w2 = t[2], h2 = t[3], a2 = t[4];

    float area1 = w1 * h1;
    float area2 = w2 * h2;

    // Box1's local frame: box1 -> axis-aligned box [-hw,hw]x[-hh,hh].
    // Angles are bounded (|a1| < pi/2, |a2-a1| small) -> fast sincos is accurate.
    float s1, c1;
    __sincosf(a1, &s1, &c1);
    float rdx0 = x2 - x1, rdy0 = y2 - y1;
    float cx = rdx0 * c1 + rdy0 * s1;
    float cy = -rdx0 * s1 + rdy0 * c1;
    float sr, cr;
    __sincosf(a2 - a1, &sr, &cr);
    float hw2 = 0.5f * w2, hh2 = 0.5f * h2;
    float e1x = hw2 * cr, e1y = hw2 * sr;
    float e2x = -hh2 * sr, e2y = hh2 * cr;

    // box2 corners in box1 frame (CCW), compile-time indexed -> registers
    float qx[4], qy[4];
    qx[0] = cx - e1x - e2x; qy[0] = cy - e1y - e2y;
    qx[1] = cx + e1x - e2x; qy[1] = cy + e1y - e2y;
    qx[2] = cx + e1x + e2x; qy[2] = cy + e1y + e2y;
    qx[3] = cx - e1x + e2x; qy[3] = cy - e1y + e2y;

    float hw = 0.5f * w1, hh = 0.5f * h1;

    // Clamp-integration (branchless): signed area of clamp(dB2) onto box1
    // equals area(box1 ∩ box2). Two accumulators to halve the serial chain.
    float acc0 = 0.0f, acc1 = 0.0f;
    float pcx = fminf(fmaxf(qx[0], -hw), hw);
    float pcy = fminf(fmaxf(qy[0], -hh), hh);
    float firstx = pcx, firsty = pcy;

#pragma unroll
    for (int k = 0; k < 4; k++) {
        float Px = qx[k], Py = qy[k];
        int kn = (k + 1) & 3;
        float Cx = qx[kn], Cy = qy[kn];
        float Dx = Cx - Px, Dy = Cy - Py;
        float rdx = __fdividef(1.0f, Dx);
        float rdy = __fdividef(1.0f, Dy);

        // crossing params with the 4 clamp lines; __saturatef: 1 op, NaN -> 0
        float t0 = __saturatef((hw - Px) * rdx);
        float t1 = __saturatef((-hw - Px) * rdx);
        float t2 = __saturatef((hh - Py) * rdy);
        float t3 = __saturatef((-hh - Py) * rdy);

        // sort 4 (optimal 5-CE network)
        CE(t0, t1); CE(t2, t3); CE(t0, t2); CE(t1, t3); CE(t1, t2);

        // breakpoints clamped into the box; shoelace vs carried point
#pragma unroll
        for (int j = 0; j < 4; j++) {
            float tj = (j == 0) ? t0 : (j == 1) ? t1 : (j == 2) ? t2 : t3;
            float bx = fminf(fmaxf(fmaf(tj, Dx, Px), -hw), hw);
            float by = fminf(fmaxf(fmaf(tj, Dy, Py), -hh), hh);
            if (j & 1) acc1 = fmaf(pcx, by, fmaf(-pcy, bx, acc1));
            else       acc0 = fmaf(pcx, by, fmaf(-pcy, bx, acc0));
            pcx = bx; pcy = by;
        }
        // clamped far endpoint (next edge's carried point)
        float bx = fminf(fmaxf(Cx, -hw), hw);
        float by = fminf(fmaxf(Cy, -hh), hh);
        acc0 = fmaf(pcx, by, fmaf(-pcy, bx, acc0));
        pcx = bx; pcy = by;
    }
    acc1 = fmaf(pcx, firsty, fmaf(-pcy, firstx, acc1));

    float inter = 0.5f * fabsf(acc0 + acc1);
    float iou = __fdividef(inter, area1 + area2 - inter);
    iou = fmaxf(iou, 1e-6f);
    return 1.0f - iou * iou * iou;
}

__global__ void __launch_bounds__(BLOCK)
rot_iou_loss_kernel(const float* __restrict__ pred,
                    const float* __restrict__ tgt,
                    float* __restrict__ out,
                    int n, int nblocks, float inv_n) {
    int j = blockIdx.x * blockDim.x + threadIdx.x;
    int half = (n + 1) >> 1;

    // two independent elements per thread -> 2 independent dep chains (ILP)
    float loss = 0.0f;
    if (j < half) loss = pair_loss(pred, tgt, j);
    int j2 = j + half;
    if (j < half && j2 < n) loss += pair_loss(pred, tgt, j2);

    // in-block reduction (fixed order -> deterministic)
    __shared__ float sdata[BLOCK / 32];
    int tid = threadIdx.x;
    float v = loss;
#pragma unroll
    for (int off = 16; off > 0; off >>= 1)
        v += __shfl_down_sync(0xFFFFFFFFu, v, off);
    if ((tid & 31) == 0) sdata[tid >> 5] = v;
    __syncthreads();
    if (tid < 32) {
        float w = (tid < BLOCK / 32) ? sdata[tid] : 0.0f;
#pragma unroll
        for (int off = 4; off > 0; off >>= 1)
            w += __shfl_down_sync(0xFFFFFFFFu, w, off);
        if (tid == 0) g_partials[blockIdx.x] = w;
    }

    // last-block final reduction (deterministic index-order sum)
    __shared__ bool is_last;
    __threadfence();
    if (tid == 0) {
        unsigned int c = atomicAdd(&g_count, 1u);
        is_last = (c == (unsigned int)nblocks - 1u);
    }
    __syncthreads();
    if (is_last) {
        __shared__ double dd[BLOCK];
        double s = 0.0;
        for (int k = tid; k < nblocks; k += BLOCK) s += (double)g_partials[k];
        dd[tid] = s;
        __syncthreads();
#pragma unroll
        for (int st = BLOCK / 2; st > 0; st >>= 1) {
            if (tid < st) dd[tid] += dd[tid + st];
            __syncthreads();
        }
        if (tid == 0) {
            out[0] = (float)(dd[0] * (double)inv_n);
            g_count = 0;  // reset for next graph replay
        }
    }
}

extern "C" void kernel_launch(void* const* d_in, const int* in_sizes, int n_in,
                              void* d_out, int out_size) {
    const float* pred = (const float*)d_in[0];
    const float* tgt  = (const float*)d_in[1];
    int n = in_sizes[0] / 5;
    int half = (n + 1) >> 1;
    int nblocks = (half + BLOCK - 1) / BLOCK;
    rot_iou_loss_kernel<<<nblocks, BLOCK>>>(pred, tgt, (float*)d_out,
                                            n, nblocks, 1.0f / (float)n);
}

// round 6
// speedup vs baseline: 3.6294x; 1.1149x over previous
#include <cuda_runtime.h>
#include <math.h>

#define BLOCK 256
#define MAX_BLOCKS 8192

__device__ float g_partials[MAX_BLOCKS];
__device__ unsigned int g_count = 0;

// Antiderivative of clamp(x, -hw, hw):  G(x) = 0.5*clamp(x)^2 + hw*max(|x|-hw, 0)
__device__ __forceinline__ float boxG(float x, float hw) {
    float c = fminf(fmaxf(x, -hw), hw);
    float e = fmaxf(fabsf(x) - hw, 0.0f);
    return fmaf(hw, e, 0.5f * c * c);
}

// Exact contribution of one box2 edge (P, direction D, t in [0,1]) to
// the clamp-curve area integral  ∮ clampx d(clampy).
__device__ __forceinline__ float edge_int(float Px, float Py,
                                          float Dx, float Dy,
                                          float rdx, float rdy,
                                          float hw, float hh) {
    // t-window where y(t) is inside [-hh, hh], clipped to [0,1].
    float tA = (hh - Py) * rdy;
    float tB = (-hh - Py) * rdy;
    float A = __saturatef(fminf(tA, tB));
    float B = __saturatef(fmaxf(tA, tB));
    float xA = fmaf(A, Dx, Px);
    float xB = fmaf(B, Dx, Px);
    return Dy * (rdx * (boxG(xB, hw) - boxG(xA, hw)));
}

__device__ __forceinline__ float safe_dir(float d) {
    return copysignf(fmaxf(fabsf(d), 1e-8f), d);
}

__global__ void __launch_bounds__(BLOCK)
rot_iou_loss_kernel(const float* __restrict__ pred,
                    const float* __restrict__ tgt,
                    float* __restrict__ out,
                    int n, int nblocks, float inv_n) {
    int i = blockIdx.x * blockDim.x + threadIdx.x;
    float loss = 0.0f;
    if (i < n) {
        const float* p = pred + 5ll * i;
        const float* t = tgt + 5ll * i;
        float x1 = p[0], y1 = p[1], w1 = p[2], h1 = p[3], a1 = p[4];
        float x2 = t[0], y2 = t[1], w2 = t[2], h2 = t[3], a2 = t[4];

        float area1 = w1 * h1;
        float area2 = w2 * h2;

        // Box1's local frame: box1 -> axis-aligned [-hw,hw]x[-hh,hh].
        float s1, c1;
        __sincosf(a1, &s1, &c1);
        float rx = x2 - x1, ry = y2 - y1;
        float cx = rx * c1 + ry * s1;
        float cy = -rx * s1 + ry * c1;
        float sr, cr;
        __sincosf(a2 - a1, &sr, &cr);
        float hw2 = 0.5f * w2, hh2 = 0.5f * h2;
        float e1x = hw2 * cr, e1y = hw2 * sr;
        float e2x = -hh2 * sr, e2y = hh2 * cr;

        // box2 corners (CCW) in box1 frame
        float q0x = cx - e1x - e2x, q0y = cy - e1y - e2y;
        float q1x = cx + e1x - e2x, q1y = cy + e1y - e2y;
        float q2x = cx + e1x + e2x, q2y = cy + e1y + e2y;
        float q3x = cx - e1x + e2x, q3y = cy - e1y + e2y;

        // Edge directions: edge0 = q0->q1 = 2*e1, edge1 = q1->q2 = 2*e2,
        // edge2 = -edge0 dir, edge3 = -edge1 dir. Degeneracy-floored.
        float D1x = safe_dir(2.0f * e1x), D1y = safe_dir(2.0f * e1y);
        float D2x = safe_dir(2.0f * e2x), D2y = safe_dir(2.0f * e2y);
        float r1x = __fdividef(1.0f, D1x), r1y = __fdividef(1.0f, D1y);
        float r2x = __fdividef(1.0f, D2x), r2y = __fdividef(1.0f, D2y);

        float hw = 0.5f * w1, hh = 0.5f * h1;

        // Four independent analytic edge integrals (wide DAG -> ILP).
        float i0 = edge_int(q0x, q0y,  D1x,  D1y,  r1x,  r1y, hw, hh);
        float i1 = edge_int(q1x, q1y,  D2x,  D2y,  r2x,  r2y, hw, hh);
        float i2 = edge_int(q2x, q2y, -D1x, -D1y, -r1x, -r1y, hw, hh);
        float i3 = edge_int(q3x, q3y, -D2x, -D2y, -r2x, -r2y, hw, hh);

        float inter = fabsf((i0 + i2) + (i1 + i3));

        float iou = __fdividef(inter, area1 + area2 - inter);
        iou = fmaxf(iou, 1e-6f);
        loss = 1.0f - iou * iou * iou;
    }

    // in-block reduction (fixed order -> deterministic)
    __shared__ float sdata[BLOCK / 32];
    int tid = threadIdx.x;
    float v = loss;
#pragma unroll
    for (int off = 16; off > 0; off >>= 1)
        v += __shfl_down_sync(0xFFFFFFFFu, v, off);
    if ((tid & 31) == 0) sdata[tid >> 5] = v;
    __syncthreads();
    if (tid < 32) {
        float w = (tid < BLOCK / 32) ? sdata[tid] : 0.0f;
#pragma unroll
        for (int off = 4; off > 0; off >>= 1)
            w += __shfl_down_sync(0xFFFFFFFFu, w, off);
        if (tid == 0) g_partials[blockIdx.x] = w;
    }

    // last-block final reduction (deterministic index-order sum)
    __shared__ bool is_last;
    __threadfence();
    if (tid == 0) {
        unsigned int c = atomicAdd(&g_count, 1u);
        is_last = (c == (unsigned int)nblocks - 1u);
    }
    __syncthreads();
    if (is_last) {
        __shared__ double dd[BLOCK];
        double s = 0.0;
        for (int k = tid; k < nblocks; k += BLOCK) s += (double)g_partials[k];
        dd[tid] = s;
        __syncthreads();
#pragma unroll
        for (int st = BLOCK / 2; st > 0; st >>= 1) {
            if (tid < st) dd[tid] += dd[tid + st];
            __syncthreads();
        }
        if (tid == 0) {
            out[0] = (float)(dd[0] * (double)inv_n);
            g_count = 0;  // reset for next graph replay
        }
    }
}

extern "C" void kernel_launch(void* const* d_in, const int* in_sizes, int n_in,
                              void* d_out, int out_size) {
    const float* pred = (const float*)d_in[0];
    const float* tgt  = (const float*)d_in[1];
    int n = in_sizes[0] / 5;
    int nblocks = (n + BLOCK - 1) / BLOCK;
    rot_iou_loss_kernel<<<nblocks, BLOCK>>>(pred, tgt, (float*)d_out,
                                            n, nblocks, 1.0f / (float)n);
}